// round 16
// baseline (speedup 1.0000x reference)
#include <cuda_runtime.h>
#include <cuda_bf16.h>
#include <cstdint>

// CumulativeNormalizer: x [32, 512, 4000] fp32.
// out[b,f,t] = (x[t] - mean(x[0..t])) / sqrt(var(x[0..t]) + 1e-4)
//
// One 128-thread block per row. NO bulk data staging: only per-float4
// (sum, sumsq) arrays (2 x 1000 floats = 8 KB) go through shared.
//   P1: coalesced striped LDG.128, per-float4 sums -> smem (coalesced STS)
//   P2: block scan of the 1000 sums (thread-local 8 + warp scan + combine),
//       exclusive prefixes written back in place
//   P3: re-load x (L2-resident), read own exclusive prefix, normalize,
//       coalesced striped STG.128 direct to global.
// 8 KB smem + <=32 regs -> 16 blocks/SM, 100% warp occupancy.
// Identity: out = (x*c - S) * rsqrt(c*Q - S^2 + eps*c^2)  -> 1 MUFU/elem.

#define FRAMES  4000
#define ROWS    (32 * 512)
#define EPS     1e-4f
#define THREADS 128
#define VEC4    (FRAMES / 4)     // 1000 float4 per row
#define ACTIVE  125              // 125 threads * 8 sums in the scan phase
#define NWARPS  4

__global__ __launch_bounds__(THREADS, 16)
void cumnorm_kernel(const float* __restrict__ x, float* __restrict__ out) {
    __shared__ float ssum[VEC4];     // per-float4 sum   -> exclusive prefix
    __shared__ float qsum[VEC4];     // per-float4 sumsq -> exclusive prefix
    __shared__ float swS[NWARPS];
    __shared__ float swQ[NWARPS];

    const int tid  = threadIdx.x;
    const int lane = tid & 31;
    const int w    = tid >> 5;
    const int row  = blockIdx.x;

    const float4* __restrict__ xr4 = reinterpret_cast<const float4*>(x)
                                     + (size_t)row * VEC4;
    float4*       __restrict__ yr4 = reinterpret_cast<float4*>(out)
                                     + (size_t)row * VEC4;

    // ---- P1: coalesced striped load, per-float4 sums -> smem ----
    #pragma unroll
    for (int k = 0; k < 8; k++) {
        const int i4 = tid + THREADS * k;
        if (i4 < VEC4) {
            const float4 v = __ldg(xr4 + i4);
            float s = v.x + v.y;
            s += v.z + v.w;
            float q = v.x * v.x;
            q = fmaf(v.y, v.y, q);
            q = fmaf(v.z, v.z, q);
            q = fmaf(v.w, v.w, q);
            ssum[i4] = s;
            qsum[i4] = q;
        }
    }
    __syncthreads();

    // ---- P2: scan the 1000 sums; write exclusive prefixes in place ----
    float ls[8], lq[8];
    float S = 0.f, Q = 0.f;
    if (tid < ACTIVE) {
        const int b0 = tid * 8;
        #pragma unroll
        for (int j = 0; j < 8; j++) {
            S += ssum[b0 + j];
            Q += qsum[b0 + j];
            ls[j] = S;               // inclusive local prefix
            lq[j] = Q;
        }
    }
    const unsigned FULL = 0xFFFFFFFFu;
    float is = S, iq = Q;
    #pragma unroll
    for (int off = 1; off < 32; off <<= 1) {
        const float ts = __shfl_up_sync(FULL, is, off);
        const float tq = __shfl_up_sync(FULL, iq, off);
        if (lane >= off) { is += ts; iq += tq; }
    }
    if (lane == 31) { swS[w] = is; swQ[w] = iq; }
    __syncthreads();

    float offS = 0.f, offQ = 0.f;
    #pragma unroll
    for (int ww = 0; ww < NWARPS - 1; ww++) {
        if (ww < w) { offS += swS[ww]; offQ += swQ[ww]; }
    }
    if (tid < ACTIVE) {
        const int b0 = tid * 8;
        const float baseS = offS + (is - S);   // exclusive before this block of 8
        const float baseQ = offQ + (iq - Q);
        ssum[b0] = baseS;                      // exclusive prefix per float4
        qsum[b0] = baseQ;
        #pragma unroll
        for (int j = 1; j < 8; j++) {
            ssum[b0 + j] = baseS + ls[j - 1];
            qsum[b0 + j] = baseQ + lq[j - 1];
        }
    }
    __syncthreads();

    // ---- P3: reload x (L2 hit), normalize, coalesced direct store ----
    #pragma unroll
    for (int k = 0; k < 8; k++) {
        const int i4 = tid + THREADS * k;
        if (i4 < VEC4) {
            const float4 v = __ldg(xr4 + i4);
            float s = ssum[i4];
            float q = qsum[i4];
            float c = (float)(4 * i4 + 1);
            float4 o;
            {   s += v.x; q = fmaf(v.x, v.x, q);
                float t = fmaf(c, q, -s * s); t = fmaf(EPS * c, c, t);
                o.x = fmaf(v.x, c, -s) * rsqrtf(t); c += 1.0f; }
            {   s += v.y; q = fmaf(v.y, v.y, q);
                float t = fmaf(c, q, -s * s); t = fmaf(EPS * c, c, t);
                o.y = fmaf(v.y, c, -s) * rsqrtf(t); c += 1.0f; }
            {   s += v.z; q = fmaf(v.z, v.z, q);
                float t = fmaf(c, q, -s * s); t = fmaf(EPS * c, c, t);
                o.z = fmaf(v.z, c, -s) * rsqrtf(t); c += 1.0f; }
            {   s += v.w; q = fmaf(v.w, v.w, q);
                float t = fmaf(c, q, -s * s); t = fmaf(EPS * c, c, t);
                o.w = fmaf(v.w, c, -s) * rsqrtf(t); }
            __stcs(yr4 + i4, o);
        }
    }
}

extern "C" void kernel_launch(void* const* d_in, const int* in_sizes, int n_in,
                              void* d_out, int out_size) {
    const float* x = (const float*)d_in[0];
    float* out = (float*)d_out;
    (void)in_sizes; (void)n_in; (void)out_size;

    cumnorm_kernel<<<ROWS, THREADS>>>(x, out);   // one block per row
}